// round 7
// baseline (speedup 1.0000x reference)
#include <cuda_runtime.h>
#include <cuda_fp16.h>

// AdditiveAttention: B=4, Q=512, K=512, H=256, E=256, DV=256
// s[b,q,k] = sum_h w_h tanh(q_h + k_h), softmax over k, @ values.
//
// tanh(q+k) expanded as odd-harmonic sine series (reflect-periodized on L=9):
//   tanh(s) ~= sum_t b_t sin(w_t s),  w_t = (2t+1)*pi/18,  t = 0..13
// sin(w(q+k)) = sin(wq)cos(wk) + cos(wq)sin(wk)  ->  scores = A @ B^T,
// inner dim KD = 256 h * 14 freq * 2 trig = 7168, fp16 HMMA, fp32 accum.

#define BB 4
#define QQ 512
#define KK 512
#define HH 256
#define EE 256
#define DVV 256
#define NF 14
#define KD 7168          // 14 * 512
#define KD_HALF 3584

// scratch (device globals: no allocations allowed)
__device__ float4 g_qv[BB * QQ * HH / 4];            // q_proj fp32, 2 MB
__device__ float4 g_kv[BB * KK * HH / 4];            // k_proj fp32, 2 MB
__device__ uint4  g_af[(size_t)2048 * KD / 8];       // A features fp16, 29.4 MB
__device__ uint4  g_bf[(size_t)2048 * KD / 8];       // B features fp16, 29.4 MB
__device__ float4 g_sv0[BB * QQ * KK / 4];           // score partials (ksplit 0), 4 MB
__device__ float4 g_sv1[BB * QQ * KK / 4];           // score partials (ksplit 1), 4 MB
__device__ float  g_bcoef[NF];                       // Fourier coefficients

// ---------------------------------------------------------------------------
// PTX helpers
// ---------------------------------------------------------------------------
__device__ __forceinline__ unsigned sptr(const void* p) {
    return (unsigned)__cvta_generic_to_shared(p);
}
__device__ __forceinline__ void ldsm4(unsigned& r0, unsigned& r1,
                                      unsigned& r2, unsigned& r3, unsigned a) {
    asm volatile("ldmatrix.sync.aligned.m8n8.x4.shared.b16 {%0,%1,%2,%3}, [%4];"
                 : "=r"(r0), "=r"(r1), "=r"(r2), "=r"(r3) : "r"(a));
}
__device__ __forceinline__ void mma16816(float* c, const unsigned* a,
                                         unsigned b0, unsigned b1) {
    asm volatile("mma.sync.aligned.m16n8k16.row.col.f32.f16.f16.f32 "
                 "{%0,%1,%2,%3}, {%4,%5,%6,%7}, {%8,%9}, {%0,%1,%2,%3};"
                 : "+f"(c[0]), "+f"(c[1]), "+f"(c[2]), "+f"(c[3])
                 : "r"(a[0]), "r"(a[1]), "r"(a[2]), "r"(a[3]), "r"(b0), "r"(b1));
}
__device__ __forceinline__ void cpasync16(unsigned s, const void* g) {
    asm volatile("cp.async.cg.shared.global [%0], [%1], 16;" :: "r"(s), "l"(g));
}
__device__ __forceinline__ void cpcommit() {
    asm volatile("cp.async.commit_group;");
}
template<int N> __device__ __forceinline__ void cpwait() {
    asm volatile("cp.async.wait_group %0;" :: "n"(N));
}

// ---------------------------------------------------------------------------
// Fourier coefficients: b_t = (2/L) * int_0^L tanh(s) sin(w_t s) ds, L = 9.
// 14 warps, one per coefficient; 8192-point midpoint rule (error ~1e-5).
// ---------------------------------------------------------------------------
__global__ void coef_kernel()
{
    const int warp = threadIdx.x >> 5, lane = threadIdx.x & 31;
    const float L = 9.0f;
    const float w = (2 * warp + 1) * (3.14159265358979e0f / 18.0f);
    float sum = 0.f;
    for (int i = lane; i < 8192; i += 32) {
        float s = (i + 0.5f) * (L / 8192.f);
        sum += tanhf(s) * sinf(w * s);
    }
#pragma unroll
    for (int o = 16; o > 0; o >>= 1)
        sum += __shfl_down_sync(0xffffffffu, sum, o);
    if (lane == 0) g_bcoef[warp] = sum * (2.f / 8192.f);
}

// ---------------------------------------------------------------------------
// Projection GEMM (R3 measured-best): C[r][h] = sum_e A[r][e] * W[h][e]
// ---------------------------------------------------------------------------
__global__ __launch_bounds__(256) void proj_kernel(
    const float* __restrict__ Aq, const float* __restrict__ Wq,
    const float* __restrict__ Ak, const float* __restrict__ Wk)
{
    const float* A; const float* W; float* C;
    if (blockIdx.z == 0) { A = Aq; W = Wq; C = (float*)g_qv; }
    else                 { A = Ak; W = Wk; C = (float*)g_kv; }

    const int row0 = blockIdx.x * 64;
    const int col0 = blockIdx.y * 64;

    __shared__ __align__(16) float As[32][68];
    __shared__ __align__(16) float Ws[32][68];

    const int tid = threadIdx.x;
    const int tx = tid & 15;
    const int ty = tid >> 4;

    float c[4][4];
#pragma unroll
    for (int i = 0; i < 4; ++i)
#pragma unroll
        for (int j = 0; j < 4; ++j) c[i][j] = 0.0f;

    for (int e0 = 0; e0 < EE; e0 += 32) {
        __syncthreads();
#pragma unroll
        for (int i = 0; i < 2; ++i) {
            const int idx = tid + i * 256;
            const int r  = idx >> 3;
            const int e8 = idx & 7;
            float4 va = *(const float4*)(A + (size_t)(row0 + r) * EE + e0 + 4 * e8);
            As[4 * e8 + 0][r] = va.x;
            As[4 * e8 + 1][r] = va.y;
            As[4 * e8 + 2][r] = va.z;
            As[4 * e8 + 3][r] = va.w;
            float4 vw = *(const float4*)(W + (size_t)(col0 + r) * EE + e0 + 4 * e8);
            Ws[4 * e8 + 0][r] = vw.x;
            Ws[4 * e8 + 1][r] = vw.y;
            Ws[4 * e8 + 2][r] = vw.z;
            Ws[4 * e8 + 3][r] = vw.w;
        }
        __syncthreads();
#pragma unroll
        for (int e = 0; e < 32; ++e) {
            float4 a4 = *(const float4*)(&As[e][4 * ty]);
            float4 w4 = *(const float4*)(&Ws[e][4 * tx]);
            float av[4] = {a4.x, a4.y, a4.z, a4.w};
            float wv[4] = {w4.x, w4.y, w4.z, w4.w};
#pragma unroll
            for (int i = 0; i < 4; ++i)
#pragma unroll
                for (int j = 0; j < 4; ++j)
                    c[i][j] = fmaf(av[i], wv[j], c[i][j]);
        }
    }

#pragma unroll
    for (int i = 0; i < 4; ++i) {
        float4 o = make_float4(c[i][0], c[i][1], c[i][2], c[i][3]);
        *(float4*)(C + (size_t)(row0 + 4 * ty + i) * HH + col0 + 4 * tx) = o;
    }
}

// ---------------------------------------------------------------------------
// Feature kernel: sin/cos of 14 odd harmonics via Chebyshev recurrence
// (1 sincos MUFU pair per element). Layout: kd = t*512 + 2h + trig.
//   A[q][kd]: (w_h*b_t*sin(w_t q_h), w_h*b_t*cos(w_t q_h))
//   B[k][kd]: (cos(w_t k_h),         sin(w_t k_h))
// -> sum_kd A*B = sum_t,h w b sin(w_t (q_h + k_h)).
// Grid: (2048 rows, 2 mats), block 256 = h. All LDG/STG coalesced.
// ---------------------------------------------------------------------------
__global__ __launch_bounds__(256) void feature_kernel(const float* __restrict__ w_v)
{
    const int row = blockIdx.x;
    const int mat = blockIdx.y;
    const int h   = threadIdx.x;

    const float x = (mat == 0 ? (const float*)g_qv
                              : (const float*)g_kv)[(size_t)row * HH + h];
    const float p = 0.17453292519943295f * x;   // pi/18
    float s1 = __sinf(p), c1 = __cosf(p);
    float t2 = 2.f * (2.f * c1 * c1 - 1.f);     // 2*cos(2p)

    const float w = (mat == 0) ? w_v[h] : 0.f;

    __half2* dst = (__half2*)(mat == 0 ? (void*)g_af : (void*)g_bf)
                 + (size_t)row * (KD / 2) + h;

    float sp = -s1, cp = c1;   // j = -1
    float sc =  s1, cc = c1;   // j = +1
#pragma unroll
    for (int t = 0; t < NF; ++t) {
        if (mat == 0) {
            float wb = w * g_bcoef[t];
            dst[t * 256] = __floats2half2_rn(wb * sc, wb * cc);
        } else {
            dst[t * 256] = __floats2half2_rn(cc, sc);
        }
        float sn = t2 * sc - sp;
        float cn = t2 * cc - cp;
        sp = sc; cp = cc; sc = sn; cc = cn;
    }
}

// ---------------------------------------------------------------------------
// Scores GEMM: C[q,k] = A[q,:] . B[k,:], fp16 HMMA (m16n8k16), fp32 accum.
// 128 blocks = b(4) x qt(4) x kt(4) x ksplit(2); 256 threads = 8 warps (2x4);
// block tile 128x128, warp tile 64x32, kd chunks of 32, cp.async double buffer,
// XOR-swizzled smem (conflict-free cp.async stores AND ldmatrix reads).
// ---------------------------------------------------------------------------
__global__ __launch_bounds__(256) void gemm_kernel()
{
    __shared__ __align__(16) __half sa[2][128 * 32];
    __shared__ __align__(16) __half sb[2][128 * 32];

    const int tid  = threadIdx.x;
    const int warp = tid >> 5, lane = tid & 31;
    const int wm = warp >> 2;        // 0..1 -> m offset wm*64
    const int wn = warp & 3;         // 0..3 -> n offset wn*32

    const int bx = blockIdx.x;
    const int ks = bx & 1;
    const int kt = (bx >> 1) & 3;
    const int qt = (bx >> 3) & 3;
    const int b  = bx >> 5;

    const __half* Ag = (const __half*)g_af + ((size_t)(b * 512 + qt * 128)) * KD + ks * KD_HALF;
    const __half* Bg = (const __half*)g_bf + ((size_t)(b * 512 + kt * 128)) * KD + ks * KD_HALF;

    float acc[16][4];
#pragma unroll
    for (int i = 0; i < 16; ++i)
#pragma unroll
        for (int j = 0; j < 4; ++j) acc[i][j] = 0.f;

    // swizzled 16B-chunk offset (halfs): (r, c8) -> r*32 + ((c8 ^ ((r>>1)&3))<<3)
#define SWZ(r, c8) ((r) * 32 + ((unsigned)((c8) ^ (((r) >> 1) & 3)) << 3))

    const int NC = KD_HALF / 32;   // 112 chunks

    // prefetch chunk 0
    {
#pragma unroll
        for (int i = 0; i < 2; ++i) {
            int idx = tid + i * 256;
            int r = idx >> 2, c8 = idx & 3;
            cpasync16(sptr(&sa[0][SWZ(r, c8)]), Ag + (size_t)r * KD + c8 * 8);
            cpasync16(sptr(&sb[0][SWZ(r, c8)]), Bg + (size_t)r * KD + c8 * 8);
        }
        cpcommit();
    }

    for (int c = 0; c < NC; ++c) {
        const int buf = c & 1;
        if (c + 1 < NC) {
            const int cc = (c + 1) * 32;
#pragma unroll
            for (int i = 0; i < 2; ++i) {
                int idx = tid + i * 256;
                int r = idx >> 2, c8 = idx & 3;
                cpasync16(sptr(&sa[buf ^ 1][SWZ(r, c8)]), Ag + (size_t)r * KD + cc + c8 * 8);
                cpasync16(sptr(&sb[buf ^ 1][SWZ(r, c8)]), Bg + (size_t)r * KD + cc + c8 * 8);
            }
            cpcommit();
            cpwait<1>();
        } else {
            cpwait<0>();
        }
        __syncthreads();

#pragma unroll
        for (int kk = 0; kk < 2; ++kk) {
            const int kc8 = kk * 2;   // 16-half step -> base c8 (0 or 2)
            unsigned af[4][4];
#pragma unroll
            for (int mt = 0; mt < 4; ++mt) {
                int r  = wm * 64 + mt * 16 + (lane & 15);
                int c8 = kc8 + (lane >> 4);
                ldsm4(af[mt][0], af[mt][1], af[mt][2], af[mt][3],
                      sptr(&sa[buf][SWZ(r, c8)]));
            }
            unsigned bf[4][2];
#pragma unroll
            for (int p = 0; p < 2; ++p) {
                int n  = wn * 32 + p * 16 + (lane & 7) + ((lane >> 4) << 3);
                int c8 = kc8 + ((lane >> 3) & 1);
                unsigned r0, r1, r2, r3;
                ldsm4(r0, r1, r2, r3, sptr(&sb[buf][SWZ(n, c8)]));
                bf[2 * p][0] = r0; bf[2 * p][1] = r1;
                bf[2 * p + 1][0] = r2; bf[2 * p + 1][1] = r3;
            }
#pragma unroll
            for (int mt = 0; mt < 4; ++mt)
#pragma unroll
                for (int nt = 0; nt < 4; ++nt)
                    mma16816(acc[mt * 4 + nt], af[mt], bf[nt][0], bf[nt][1]);
        }
        __syncthreads();
    }
#undef SWZ

    float* Cg = (ks ? (float*)g_sv1 : (float*)g_sv0)
              + (size_t)b * QQ * KK + (size_t)(qt * 128) * KK + kt * 128;
#pragma unroll
    for (int mt = 0; mt < 4; ++mt)
#pragma unroll
        for (int nt = 0; nt < 4; ++nt) {
            int row = wm * 64 + mt * 16 + (lane >> 2);
            int col = wn * 32 + nt * 8 + (lane & 3) * 2;
            float* d = Cg + (size_t)row * KK + col;
            *(float2*)d              = make_float2(acc[mt * 4 + nt][0], acc[mt * 4 + nt][1]);
            *(float2*)(d + 8 * KK)   = make_float2(acc[mt * 4 + nt][2], acc[mt * 4 + nt][3]);
        }
}

// ---------------------------------------------------------------------------
// Softmax over K + attn @ V. Sums the two k-split partial score buffers.
// Grid: 128 blocks = b(4) x qtile(32, 16 queries). Block: 512 threads.
// ---------------------------------------------------------------------------
__global__ __launch_bounds__(512) void softmax_av_kernel(
    const float* __restrict__ values, float* __restrict__ out)
{
    __shared__ __align__(16) float p[16 * 512];
    __shared__ float invs[16];

    const int bx = blockIdx.x;
    const int b  = bx >> 5;
    const int qt = bx & 31;
    const int tid = threadIdx.x;

    {
        const size_t off = (size_t)(b * QQ + qt * 16) * KK;
        const float4* s0 = (const float4*)((const float*)g_sv0 + off);
        const float4* s1 = (const float4*)((const float*)g_sv1 + off);
        float4* dst = (float4*)p;
#pragma unroll
        for (int j = 0; j < 4; ++j) {
            float4 a = s0[tid + j * 512];
            float4 c = s1[tid + j * 512];
            dst[tid + j * 512] = make_float4(a.x + c.x, a.y + c.y, a.z + c.z, a.w + c.w);
        }
    }
    __syncthreads();

    {
        const int w = tid >> 5, lane = tid & 31;
        float* row = p + w * 512;
        float m = -1e30f;
#pragma unroll
        for (int j = 0; j < 16; ++j) m = fmaxf(m, row[lane + 32 * j]);
#pragma unroll
        for (int o = 16; o > 0; o >>= 1)
            m = fmaxf(m, __shfl_xor_sync(0xffffffffu, m, o));
        float sum = 0.0f;
#pragma unroll
        for (int j = 0; j < 16; ++j) {
            float e = __expf(row[lane + 32 * j] - m);
            row[lane + 32 * j] = e;
            sum += e;
        }
#pragma unroll
        for (int o = 16; o > 0; o >>= 1)
            sum += __shfl_xor_sync(0xffffffffu, sum, o);
        if (lane == 0) invs[w] = 1.0f / sum;
    }
    __syncthreads();

    const int dq = tid & 63;
    const int qp = tid >> 6;
    const float* p0r = p + (2 * qp) * 512;
    const float* p1r = p + (2 * qp + 1) * 512;
    const float4* V = (const float4*)(values + (size_t)b * KK * DVV);

    float4 acc0 = make_float4(0.f, 0.f, 0.f, 0.f);
    float4 acc1 = make_float4(0.f, 0.f, 0.f, 0.f);

#pragma unroll 4
    for (int k = 0; k < KK; ++k) {
        const float4 v = V[k * (DVV / 4) + dq];
        const float a = p0r[k];
        const float c = p1r[k];
        acc0.x = fmaf(a, v.x, acc0.x);
        acc0.y = fmaf(a, v.y, acc0.y);
        acc0.z = fmaf(a, v.z, acc0.z);
        acc0.w = fmaf(a, v.w, acc0.w);
        acc1.x = fmaf(c, v.x, acc1.x);
        acc1.y = fmaf(c, v.y, acc1.y);
        acc1.z = fmaf(c, v.z, acc1.z);
        acc1.w = fmaf(c, v.w, acc1.w);
    }

    const float i0 = invs[2 * qp];
    const float i1 = invs[2 * qp + 1];
    acc0.x *= i0; acc0.y *= i0; acc0.z *= i0; acc0.w *= i0;
    acc1.x *= i1; acc1.y *= i1; acc1.z *= i1; acc1.w *= i1;

    const int q0 = qt * 16 + 2 * qp;
    *(float4*)(out + (size_t)(b * QQ + q0) * DVV + 4 * dq)     = acc0;
    *(float4*)(out + (size_t)(b * QQ + q0 + 1) * DVV + 4 * dq) = acc1;
}

// ---------------------------------------------------------------------------
extern "C" void kernel_launch(void* const* d_in, const int* in_sizes, int n_in,
                              void* d_out, int out_size)
{
    const float* queries = (const float*)d_in[0];
    const float* keys    = (const float*)d_in[1];
    const float* values  = (const float*)d_in[2];
    const float* W_q     = (const float*)d_in[3];
    const float* W_k     = (const float*)d_in[4];
    const float* w_v     = (const float*)d_in[5];
    float* out = (float*)d_out;

    coef_kernel<<<1, 448>>>();
    proj_kernel<<<dim3(32, 4, 2), 256>>>(queries, W_q, keys, W_k);
    feature_kernel<<<dim3(2048, 2), 256>>>(w_v);
    gemm_kernel<<<128, 256>>>();
    softmax_av_kernel<<<128, 512>>>(values, out);
}

// round 9
// speedup vs baseline: 1.1132x; 1.1132x over previous
#include <cuda_runtime.h>
#include <cuda_fp16.h>

// AdditiveAttention: B=4, Q=512, K=512, H=256, E=256, DV=256
// tanh(q+k) = sum_t b_t sin(w_t(q+k)),  w_t=(2t+1)pi/18, t=0..NF-1 (L=9)
// sin(w(q+k)) = sin(wq)cos(wk)+cos(wq)sin(wk)  ->  scores = A @ B^T (fp16 HMMA)
// A[q,kd] = w_h*(sin,cos)(w_t q_h);  B[k,kd] = b_t*(cos,sin)(w_t k_h)
// kd = t*512 + 2h + trig;  KD = 2*NF*H.  NF=14 (measured rel_err 3.8e-4).

#define BB 4
#define QQ 512
#define KK 512
#define HH 256
#define EE 256
#define DVV 256
#define NF 14
#define KD 7168          // 14 * 512
#define KDQ 1792         // KD / 4 k-splits

// scratch (device globals: no allocations allowed)
__device__ float4 g_qv[BB * QQ * HH / 4];            // q_proj fp32, 2 MB
__device__ float4 g_kv[BB * KK * HH / 4];            // k_proj fp32, 2 MB
__device__ uint4  g_af[(size_t)2048 * KD / 8];       // A features fp16, 29.4 MB
__device__ uint4  g_bf[(size_t)2048 * KD / 8];       // B features fp16, 29.4 MB
__device__ float4 g_sv0[BB * QQ * KK / 4];           // score partial ks=0, 4 MB
__device__ float4 g_sv1[BB * QQ * KK / 4];
__device__ float4 g_sv2[BB * QQ * KK / 4];
__device__ float4 g_sv3[BB * QQ * KK / 4];
__device__ float  g_bcoef[NF];

// ---------------------------------------------------------------------------
__device__ __forceinline__ float tanh_fast(float x) {
    float y; asm("tanh.approx.f32 %0, %1;" : "=f"(y) : "f"(x)); return y;
}
__device__ __forceinline__ unsigned sptr(const void* p) {
    return (unsigned)__cvta_generic_to_shared(p);
}
__device__ __forceinline__ void ldsm4(unsigned& r0, unsigned& r1,
                                      unsigned& r2, unsigned& r3, unsigned a) {
    asm volatile("ldmatrix.sync.aligned.m8n8.x4.shared.b16 {%0,%1,%2,%3}, [%4];"
                 : "=r"(r0), "=r"(r1), "=r"(r2), "=r"(r3) : "r"(a));
}
__device__ __forceinline__ void mma16816(float* c, const unsigned* a,
                                         unsigned b0, unsigned b1) {
    asm volatile("mma.sync.aligned.m16n8k16.row.col.f32.f16.f16.f32 "
                 "{%0,%1,%2,%3}, {%4,%5,%6,%7}, {%8,%9}, {%0,%1,%2,%3};"
                 : "+f"(c[0]), "+f"(c[1]), "+f"(c[2]), "+f"(c[3])
                 : "r"(a[0]), "r"(a[1]), "r"(a[2]), "r"(a[3]), "r"(b0), "r"(b1));
}
__device__ __forceinline__ void cpasync16(unsigned s, const void* g) {
    asm volatile("cp.async.cg.shared.global [%0], [%1], 16;" :: "r"(s), "l"(g));
}
__device__ __forceinline__ void cpcommit() { asm volatile("cp.async.commit_group;"); }
template<int N> __device__ __forceinline__ void cpwait() {
    asm volatile("cp.async.wait_group %0;" :: "n"(N));
}

// ---------------------------------------------------------------------------
// Fourier coefficients: b_t = (2/9) int_0^9 tanh(s) sin(w_t s) ds.
// 14 warps (one per t), 4096-pt midpoint, MUFU tanh/sin (bias < 2e-5).
// ---------------------------------------------------------------------------
__global__ void coef_kernel()
{
    const int warp = threadIdx.x >> 5, lane = threadIdx.x & 31;
    const float w = (2 * warp + 1) * 0.17453292519943295f;  // (2t+1)*pi/18
    float sum = 0.f;
#pragma unroll 4
    for (int i = lane; i < 4096; i += 32) {
        float s = (i + 0.5f) * (9.0f / 4096.f);
        sum += tanh_fast(s) * __sinf(w * s);
    }
#pragma unroll
    for (int o = 16; o > 0; o >>= 1)
        sum += __shfl_down_sync(0xffffffffu, sum, o);
    if (lane == 0) g_bcoef[warp] = sum * (2.f / 4096.f);
}

// ---------------------------------------------------------------------------
// Projection GEMM (measured-best): C[r][h] = sum_e A[r][e] * W[h][e]
// ---------------------------------------------------------------------------
__global__ __launch_bounds__(256) void proj_kernel(
    const float* __restrict__ Aq, const float* __restrict__ Wq,
    const float* __restrict__ Ak, const float* __restrict__ Wk)
{
    const float* A; const float* W; float* C;
    if (blockIdx.z == 0) { A = Aq; W = Wq; C = (float*)g_qv; }
    else                 { A = Ak; W = Wk; C = (float*)g_kv; }

    const int row0 = blockIdx.x * 64;
    const int col0 = blockIdx.y * 64;

    __shared__ __align__(16) float As[32][68];
    __shared__ __align__(16) float Ws[32][68];

    const int tid = threadIdx.x;
    const int tx = tid & 15;
    const int ty = tid >> 4;

    float c[4][4];
#pragma unroll
    for (int i = 0; i < 4; ++i)
#pragma unroll
        for (int j = 0; j < 4; ++j) c[i][j] = 0.0f;

    for (int e0 = 0; e0 < EE; e0 += 32) {
        __syncthreads();
#pragma unroll
        for (int i = 0; i < 2; ++i) {
            const int idx = tid + i * 256;
            const int r  = idx >> 3;
            const int e8 = idx & 7;
            float4 va = *(const float4*)(A + (size_t)(row0 + r) * EE + e0 + 4 * e8);
            As[4 * e8 + 0][r] = va.x;
            As[4 * e8 + 1][r] = va.y;
            As[4 * e8 + 2][r] = va.z;
            As[4 * e8 + 3][r] = va.w;
            float4 vw = *(const float4*)(W + (size_t)(col0 + r) * EE + e0 + 4 * e8);
            Ws[4 * e8 + 0][r] = vw.x;
            Ws[4 * e8 + 1][r] = vw.y;
            Ws[4 * e8 + 2][r] = vw.z;
            Ws[4 * e8 + 3][r] = vw.w;
        }
        __syncthreads();
#pragma unroll
        for (int e = 0; e < 32; ++e) {
            float4 a4 = *(const float4*)(&As[e][4 * ty]);
            float4 w4 = *(const float4*)(&Ws[e][4 * tx]);
            float av[4] = {a4.x, a4.y, a4.z, a4.w};
            float wv[4] = {w4.x, w4.y, w4.z, w4.w};
#pragma unroll
            for (int i = 0; i < 4; ++i)
#pragma unroll
                for (int j = 0; j < 4; ++j)
                    c[i][j] = fmaf(av[i], wv[j], c[i][j]);
        }
    }

#pragma unroll
    for (int i = 0; i < 4; ++i) {
        float4 o = make_float4(c[i][0], c[i][1], c[i][2], c[i][3]);
        *(float4*)(C + (size_t)(row0 + 4 * ty + i) * HH + col0 + 4 * tx) = o;
    }
}

// ---------------------------------------------------------------------------
// Feature kernel. grid (2048 rows, 2 mats), 128 threads; thread owns 2 h.
// Chebyshev recurrence in fp32. w_h folded into the A-chain initial value;
// b_t applied on the B side in fp32 BEFORE the half2 convert (one rounding).
//   A[q][t*256+h] = (w*sin, w*cos);  B[k][t*256+h] = b_t*(cos, sin)
// ---------------------------------------------------------------------------
__global__ __launch_bounds__(128) void feature_kernel(const float* __restrict__ w_v)
{
    const int row = blockIdx.x;
    const int mat = blockIdx.y;
    const int h0  = 2 * threadIdx.x;

    const float* src = (mat == 0 ? (const float*)g_qv : (const float*)g_kv)
                     + (size_t)row * HH;
    const float x0 = src[h0], x1 = src[h0 + 1];
    const float P18 = 0.17453292519943295f;
    const float p0 = P18 * x0, p1 = P18 * x1;
    float rs0 = __sinf(p0), rc0 = __cosf(p0);
    float rs1 = __sinf(p1), rc1 = __cosf(p1);
    const float t20 = 2.f * fmaf(2.f * rc0, rc0, -1.f);
    const float t21 = 2.f * fmaf(2.f * rc1, rc1, -1.f);

    const float a0 = (mat == 0) ? w_v[h0]     : 1.f;
    const float a1 = (mat == 0) ? w_v[h0 + 1] : 1.f;

    float s0 = a0 * rs0, c0 = a0 * rc0, sp0 = -s0, cp0 = c0;
    float s1 = a1 * rs1, c1 = a1 * rc1, sp1 = -s1, cp1 = c1;

    uint2* dst = (uint2*)((__half2*)(mat == 0 ? (void*)g_af : (void*)g_bf)
               + (size_t)row * (KD / 2) + h0);

#pragma unroll
    for (int t = 0; t < NF; ++t) {
        uint2 v;
        if (mat == 0) {
            __half2 v0 = __floats2half2_rn(s0, c0);
            __half2 v1 = __floats2half2_rn(s1, c1);
            v.x = *(unsigned*)&v0; v.y = *(unsigned*)&v1;
        } else {
            const float bt = g_bcoef[t];
            __half2 v0 = __floats2half2_rn(bt * c0, bt * s0);
            __half2 v1 = __floats2half2_rn(bt * c1, bt * s1);
            v.x = *(unsigned*)&v0; v.y = *(unsigned*)&v1;
        }
        dst[t * 128] = v;   // (t*256 + h0) half2 -> /2 uint2 index

        float sn0 = fmaf(t20, s0, -sp0); float cn0 = fmaf(t20, c0, -cp0);
        float sn1 = fmaf(t21, s1, -sp1); float cn1 = fmaf(t21, c1, -cp1);
        sp0 = s0; cp0 = c0; s0 = sn0; c0 = cn0;
        sp1 = s1; cp1 = c1; s1 = sn1; c1 = cn1;
    }
}

// ---------------------------------------------------------------------------
// Scores GEMM: 256 blocks = b(4) x qt(4) x kt(4) x ks(4). 256 threads (8 warps
// 2x4), block tile 128x128, k-chunk 32, 3-stage cp.async, 1 sync per chunk.
// ---------------------------------------------------------------------------
__global__ __launch_bounds__(256, 2) void gemm_kernel()
{
    __shared__ __align__(16) __half sa[3][128 * 32];   // 24 KB
    __shared__ __align__(16) __half sb[3][128 * 32];   // 24 KB

    const int tid  = threadIdx.x;
    const int warp = tid >> 5, lane = tid & 31;
    const int wm = warp >> 2;        // m offset wm*64
    const int wn = warp & 3;         // n offset wn*32

    const int bx = blockIdx.x;
    const int ks = bx & 3;
    const int kt = (bx >> 2) & 3;
    const int qt = (bx >> 4) & 3;
    const int b  = bx >> 6;

    const __half* Ag = (const __half*)g_af + ((size_t)(b * 512 + qt * 128)) * KD + ks * KDQ;
    const __half* Bg = (const __half*)g_bf + ((size_t)(b * 512 + kt * 128)) * KD + ks * KDQ;

    float acc[16][4];
#pragma unroll
    for (int i = 0; i < 16; ++i)
#pragma unroll
        for (int j = 0; j < 4; ++j) acc[i][j] = 0.f;

#define SWZ(r, c8) ((r) * 32 + ((unsigned)((c8) ^ (((r) >> 1) & 3)) << 3))

    const int NC = KDQ / 32;   // 56 chunks

    // prefetch chunks 0,1 into stages 0,1
#pragma unroll
    for (int s = 0; s < 2; ++s) {
#pragma unroll
        for (int i = 0; i < 2; ++i) {
            int idx = tid + i * 256;
            int r = idx >> 2, c8 = idx & 3;
            cpasync16(sptr(&sa[s][SWZ(r, c8)]), Ag + (size_t)r * KD + s * 32 + c8 * 8);
            cpasync16(sptr(&sb[s][SWZ(r, c8)]), Bg + (size_t)r * KD + s * 32 + c8 * 8);
        }
        cpcommit();
    }

    for (int c = 0; c < NC; ++c) {
        if (c + 1 < NC) cpwait<1>(); else cpwait<0>();
        __syncthreads();

        if (c + 2 < NC) {
            const int st = (c + 2) % 3;
            const int cc = (c + 2) * 32;
#pragma unroll
            for (int i = 0; i < 2; ++i) {
                int idx = tid + i * 256;
                int r = idx >> 2, c8 = idx & 3;
                cpasync16(sptr(&sa[st][SWZ(r, c8)]), Ag + (size_t)r * KD + cc + c8 * 8);
                cpasync16(sptr(&sb[st][SWZ(r, c8)]), Bg + (size_t)r * KD + cc + c8 * 8);
            }
            cpcommit();
        }

        const int buf = c % 3;
#pragma unroll
        for (int kk = 0; kk < 2; ++kk) {
            const int kc8 = kk * 2;
            unsigned af[4][4];
#pragma unroll
            for (int mt = 0; mt < 4; ++mt) {
                int r  = wm * 64 + mt * 16 + (lane & 15);
                int c8 = kc8 + (lane >> 4);
                ldsm4(af[mt][0], af[mt][1], af[mt][2], af[mt][3],
                      sptr(&sa[buf][SWZ(r, c8)]));
            }
            unsigned bfr[4][2];
#pragma unroll
            for (int p = 0; p < 2; ++p) {
                int n  = wn * 32 + p * 16 + (lane & 7) + ((lane >> 4) << 3);
                int c8 = kc8 + ((lane >> 3) & 1);
                unsigned r0, r1, r2, r3;
                ldsm4(r0, r1, r2, r3, sptr(&sb[buf][SWZ(n, c8)]));
                bfr[2 * p][0] = r0; bfr[2 * p][1] = r1;
                bfr[2 * p + 1][0] = r2; bfr[2 * p + 1][1] = r3;
            }
#pragma unroll
            for (int mt = 0; mt < 4; ++mt)
#pragma unroll
                for (int nt = 0; nt < 4; ++nt)
                    mma16816(acc[mt * 4 + nt], af[mt], bfr[nt][0], bfr[nt][1]);
        }
    }
#undef SWZ

    float* Cg;
    if      (ks == 0) Cg = (float*)g_sv0;
    else if (ks == 1) Cg = (float*)g_sv1;
    else if (ks == 2) Cg = (float*)g_sv2;
    else              Cg = (float*)g_sv3;
    Cg += (size_t)b * QQ * KK + (size_t)(qt * 128) * KK + kt * 128;
#pragma unroll
    for (int mt = 0; mt < 4; ++mt)
#pragma unroll
        for (int nt = 0; nt < 4; ++nt) {
            int row = wm * 64 + mt * 16 + (lane >> 2);
            int col = wn * 32 + nt * 8 + (lane & 3) * 2;
            float* d = Cg + (size_t)row * KK + col;
            *(float2*)d            = make_float2(acc[mt * 4 + nt][0], acc[mt * 4 + nt][1]);
            *(float2*)(d + 8 * KK) = make_float2(acc[mt * 4 + nt][2], acc[mt * 4 + nt][3]);
        }
}

// ---------------------------------------------------------------------------
// Softmax over K + attn @ V; sums the 4 k-split partials.
// Grid: 128 blocks = b(4) x qtile(32, 16 queries). Block: 512 threads.
// ---------------------------------------------------------------------------
__global__ __launch_bounds__(512) void softmax_av_kernel(
    const float* __restrict__ values, float* __restrict__ out)
{
    __shared__ __align__(16) float p[16 * 512];
    __shared__ float invs[16];

    const int bx = blockIdx.x;
    const int b  = bx >> 5;
    const int qt = bx & 31;
    const int tid = threadIdx.x;

    {
        const size_t off = (size_t)(b * QQ + qt * 16) * KK;
        const float4* s0 = (const float4*)((const float*)g_sv0 + off);
        const float4* s1 = (const float4*)((const float*)g_sv1 + off);
        const float4* s2 = (const float4*)((const float*)g_sv2 + off);
        const float4* s3 = (const float4*)((const float*)g_sv3 + off);
        float4* dst = (float4*)p;
#pragma unroll
        for (int j = 0; j < 4; ++j) {
            float4 a = s0[tid + j * 512];
            float4 c = s1[tid + j * 512];
            float4 d = s2[tid + j * 512];
            float4 e = s3[tid + j * 512];
            dst[tid + j * 512] = make_float4((a.x + c.x) + (d.x + e.x),
                                             (a.y + c.y) + (d.y + e.y),
                                             (a.z + c.z) + (d.z + e.z),
                                             (a.w + c.w) + (d.w + e.w));
        }
    }
    __syncthreads();

    {
        const int w = tid >> 5, lane = tid & 31;
        float* row = p + w * 512;
        float m = -1e30f;
#pragma unroll
        for (int j = 0; j < 16; ++j) m = fmaxf(m, row[lane + 32 * j]);
#pragma unroll
        for (int o = 16; o > 0; o >>= 1)
            m = fmaxf(m, __shfl_xor_sync(0xffffffffu, m, o));
        float sum = 0.0f;
#pragma unroll
        for (int j = 0; j < 16; ++j) {
            float e = __expf(row[lane + 32 * j] - m);
            row[lane + 32 * j] = e;
            sum += e;
        }
#pragma unroll
        for (int o = 16; o > 0; o >>= 1)
            sum += __shfl_xor_sync(0xffffffffu, sum, o);
        if (lane == 0) invs[w] = 1.0f / sum;
    }
    __syncthreads();

    const int dq = tid & 63;
    const int qp = tid >> 6;
    const float* p0r = p + (2 * qp) * 512;
    const float* p1r = p + (2 * qp + 1) * 512;
    const float4* V = (const float4*)(values + (size_t)b * KK * DVV);

    float4 acc0 = make_float4(0.f, 0.f, 0.f, 0.f);
    float4 acc1 = make_float4(0.f, 0.f, 0.f, 0.f);

#pragma unroll 4
    for (int k = 0; k < KK; ++k) {
        const float4 v = V[k * (DVV / 4) + dq];
        const float a = p0r[k];
        const float c = p1r[k];
        acc0.x = fmaf(a, v.x, acc0.x);
        acc0.y = fmaf(a, v.y, acc0.y);
        acc0.z = fmaf(a, v.z, acc0.z);
        acc0.w = fmaf(a, v.w, acc0.w);
        acc1.x = fmaf(c, v.x, acc1.x);
        acc1.y = fmaf(c, v.y, acc1.y);
        acc1.z = fmaf(c, v.z, acc1.z);
        acc1.w = fmaf(c, v.w, acc1.w);
    }

    const float i0 = invs[2 * qp];
    const float i1 = invs[2 * qp + 1];
    acc0.x *= i0; acc0.y *= i0; acc0.z *= i0; acc0.w *= i0;
    acc1.x *= i1; acc1.y *= i1; acc1.z *= i1; acc1.w *= i1;

    const int q0 = qt * 16 + 2 * qp;
    *(float4*)(out + (size_t)(b * QQ + q0) * DVV + 4 * dq)     = acc0;
    *(float4*)(out + (size_t)(b * QQ + q0 + 1) * DVV + 4 * dq) = acc1;
}

// ---------------------------------------------------------------------------
extern "C" void kernel_launch(void* const* d_in, const int* in_sizes, int n_in,
                              void* d_out, int out_size)
{
    const float* queries = (const float*)d_in[0];
    const float* keys    = (const float*)d_in[1];
    const float* values  = (const float*)d_in[2];
    const float* W_q     = (const float*)d_in[3];
    const float* W_k     = (const float*)d_in[4];
    const float* w_v     = (const float*)d_in[5];
    float* out = (float*)d_out;

    coef_kernel<<<1, 32 * NF>>>();
    proj_kernel<<<dim3(32, 4, 2), 256>>>(queries, W_q, keys, W_k);
    feature_kernel<<<dim3(2048, 2), 128>>>(w_v);
    gemm_kernel<<<256, 256>>>();
    softmax_av_kernel<<<128, 512>>>(values, out);
}